// round 1
// baseline (speedup 1.0000x reference)
#include <cuda_runtime.h>

// Problem constants
#define BATCH   8
#define SEQ     1024
#define EMBED   768
#define HEADS   12
#define HDIM    64
#define ROWS    (BATCH * SEQ)        // 8192
#define QKVCOLS (3 * EMBED)          // 2304
#define ATTN_SCALE 0.125f            // 64^-0.5

// Scratch (device globals: allocation-free per harness rules)
__device__ float g_qkv[ROWS * QKVCOLS];   // [8192, 2304] = qkv projection, row-major
__device__ float g_oh [ROWS * EMBED];     // [8192, 768]  = attn @ V, head-interleaved

// ---------------------------------------------------------------------------
// Generic NT GEMM: C[m,n] = alpha * sum_k A[m*lda+k] * B[n*ldb+k] (+ bias[n])
// Tile 64x64x16, 256 threads, 4x4 per thread. All dims assumed divisible.
// ---------------------------------------------------------------------------
#define BM 64
#define BN 64
#define BK 16

__global__ void gemm_nt(const float* __restrict__ A, int lda,
                        const float* __restrict__ B, int ldb,
                        float* __restrict__ C, int ldc,
                        int K, float alpha, const float* __restrict__ bias) {
    __shared__ float As[BM][BK + 1];
    __shared__ float Bs[BN][BK + 1];
    const int tx = threadIdx.x % 16;
    const int ty = threadIdx.x / 16;
    const int m0 = blockIdx.y * BM;
    const int n0 = blockIdx.x * BN;

    float acc[4][4] = {};
    for (int k0 = 0; k0 < K; k0 += BK) {
        #pragma unroll
        for (int i = threadIdx.x; i < BM * BK; i += 256) {
            int r = i / BK, c = i % BK;
            As[r][c] = A[(long long)(m0 + r) * lda + k0 + c];
        }
        #pragma unroll
        for (int i = threadIdx.x; i < BN * BK; i += 256) {
            int r = i / BK, c = i % BK;
            Bs[r][c] = B[(long long)(n0 + r) * ldb + k0 + c];
        }
        __syncthreads();
        #pragma unroll
        for (int kk = 0; kk < BK; kk++) {
            float a[4], b[4];
            #pragma unroll
            for (int i = 0; i < 4; i++) a[i] = As[ty * 4 + i][kk];
            #pragma unroll
            for (int j = 0; j < 4; j++) b[j] = Bs[tx * 4 + j][kk];
            #pragma unroll
            for (int i = 0; i < 4; i++)
                #pragma unroll
                for (int j = 0; j < 4; j++)
                    acc[i][j] += a[i] * b[j];
        }
        __syncthreads();
    }
    #pragma unroll
    for (int i = 0; i < 4; i++) {
        #pragma unroll
        for (int j = 0; j < 4; j++) {
            int m = m0 + ty * 4 + i;
            int n = n0 + tx * 4 + j;
            float v = acc[i][j] * alpha;
            if (bias) v += bias[n];
            C[(long long)m * ldc + n] = v;
        }
    }
}

// ---------------------------------------------------------------------------
// Attention scores: per (b,h), S = scale * Q @ K^T  -> attn buffer (pre-softmax)
// Q row m: g_qkv[(b*SEQ+m)*2304 + h*64 + d]
// K row n: g_qkv[(b*SEQ+n)*2304 + 768 + h*64 + d]
// ---------------------------------------------------------------------------
__global__ void gemm_scores(const float* __restrict__ qkv,
                            float* __restrict__ attn) {
    const int z = blockIdx.z;          // 0..95
    const int b = z / HEADS;
    const int h = z % HEADS;
    const float* A = qkv + (long long)b * SEQ * QKVCOLS + h * HDIM;           // Q
    const float* B = A + EMBED;                                               // K
    float* C = attn + (long long)z * SEQ * SEQ;

    __shared__ float As[BM][BK + 1];
    __shared__ float Bs[BN][BK + 1];
    const int tx = threadIdx.x % 16;
    const int ty = threadIdx.x / 16;
    const int m0 = blockIdx.y * BM;
    const int n0 = blockIdx.x * BN;

    float acc[4][4] = {};
    for (int k0 = 0; k0 < HDIM; k0 += BK) {
        #pragma unroll
        for (int i = threadIdx.x; i < BM * BK; i += 256) {
            int r = i / BK, c = i % BK;
            As[r][c] = A[(long long)(m0 + r) * QKVCOLS + k0 + c];
        }
        #pragma unroll
        for (int i = threadIdx.x; i < BN * BK; i += 256) {
            int r = i / BK, c = i % BK;
            Bs[r][c] = B[(long long)(n0 + r) * QKVCOLS + k0 + c];
        }
        __syncthreads();
        #pragma unroll
        for (int kk = 0; kk < BK; kk++) {
            float a[4], bb[4];
            #pragma unroll
            for (int i = 0; i < 4; i++) a[i] = As[ty * 4 + i][kk];
            #pragma unroll
            for (int j = 0; j < 4; j++) bb[j] = Bs[tx * 4 + j][kk];
            #pragma unroll
            for (int i = 0; i < 4; i++)
                #pragma unroll
                for (int j = 0; j < 4; j++)
                    acc[i][j] += a[i] * bb[j];
        }
        __syncthreads();
    }
    #pragma unroll
    for (int i = 0; i < 4; i++)
        #pragma unroll
        for (int j = 0; j < 4; j++)
            C[(long long)(m0 + ty * 4 + i) * SEQ + n0 + tx * 4 + j] =
                acc[i][j] * ATTN_SCALE;
}

// ---------------------------------------------------------------------------
// Row softmax in-place on attn. One block (256 thr) per row of 1024.
// Row cached in registers: 4 values per thread.
// ---------------------------------------------------------------------------
__global__ void softmax_rows(float* __restrict__ data) {
    float* row = data + (long long)blockIdx.x * SEQ;
    const int t = threadIdx.x;
    float v[4];
    float m = -1e30f;
    #pragma unroll
    for (int i = 0; i < 4; i++) { v[i] = row[t + i * 256]; m = fmaxf(m, v[i]); }

    __shared__ float smax[8];
    #pragma unroll
    for (int o = 16; o > 0; o >>= 1) m = fmaxf(m, __shfl_xor_sync(0xffffffffu, m, o));
    if ((t & 31) == 0) smax[t >> 5] = m;
    __syncthreads();
    if (t < 8) {
        float x = smax[t];
        #pragma unroll
        for (int o = 4; o > 0; o >>= 1) x = fmaxf(x, __shfl_xor_sync(0xffu, x, o));
        if (t == 0) smax[0] = x;
    }
    __syncthreads();
    m = smax[0];

    float s = 0.f;
    #pragma unroll
    for (int i = 0; i < 4; i++) { v[i] = __expf(v[i] - m); s += v[i]; }

    __shared__ float ssum[8];
    #pragma unroll
    for (int o = 16; o > 0; o >>= 1) s += __shfl_xor_sync(0xffffffffu, s, o);
    if ((t & 31) == 0) ssum[t >> 5] = s;
    __syncthreads();
    if (t < 8) {
        float x = ssum[t];
        #pragma unroll
        for (int o = 4; o > 0; o >>= 1) x += __shfl_xor_sync(0xffu, x, o);
        if (t == 0) ssum[0] = x;
    }
    __syncthreads();
    const float inv = 1.0f / ssum[0];
    #pragma unroll
    for (int i = 0; i < 4; i++) row[t + i * 256] = v[i] * inv;
}

// ---------------------------------------------------------------------------
// PV: per (b,h), O = P(1024x1024) @ V(1024x64)   (NN gemm)
// V row m: g_qkv[(b*SEQ+m)*2304 + 1536 + h*64 + d]
// O written head-interleaved into g_oh[(b*SEQ+n)*768 + h*64 + d]
// ---------------------------------------------------------------------------
__global__ void gemm_pv(const float* __restrict__ attn,
                        const float* __restrict__ qkv,
                        float* __restrict__ oh) {
    const int z = blockIdx.z;
    const int b = z / HEADS;
    const int h = z % HEADS;
    const float* A = attn + (long long)z * SEQ * SEQ;                          // P
    const float* B = qkv + (long long)b * SEQ * QKVCOLS + 2 * EMBED + h * HDIM;// V
    float* C = oh + (long long)b * SEQ * EMBED + h * HDIM;

    __shared__ float As[BM][BK + 1];
    __shared__ float Bs[BK][BN + 1];
    const int tx = threadIdx.x % 16;
    const int ty = threadIdx.x / 16;
    const int m0 = blockIdx.y * BM;
    const int n0 = 0;  // N == 64, single tile column

    float acc[4][4] = {};
    for (int k0 = 0; k0 < SEQ; k0 += BK) {
        #pragma unroll
        for (int i = threadIdx.x; i < BM * BK; i += 256) {
            int r = i / BK, c = i % BK;
            As[r][c] = A[(long long)(m0 + r) * SEQ + k0 + c];
        }
        #pragma unroll
        for (int i = threadIdx.x; i < BK * BN; i += 256) {
            int r = i / BN, c = i % BN;
            Bs[r][c] = B[(long long)(k0 + r) * QKVCOLS + n0 + c];
        }
        __syncthreads();
        #pragma unroll
        for (int kk = 0; kk < BK; kk++) {
            float a[4], bb[4];
            #pragma unroll
            for (int i = 0; i < 4; i++) a[i] = As[ty * 4 + i][kk];
            #pragma unroll
            for (int j = 0; j < 4; j++) bb[j] = Bs[kk][tx * 4 + j];
            #pragma unroll
            for (int i = 0; i < 4; i++)
                #pragma unroll
                for (int j = 0; j < 4; j++)
                    acc[i][j] += a[i] * bb[j];
        }
        __syncthreads();
    }
    #pragma unroll
    for (int i = 0; i < 4; i++)
        #pragma unroll
        for (int j = 0; j < 4; j++)
            C[(long long)(m0 + ty * 4 + i) * EMBED + tx * 4 + j] = acc[i][j];
}

// ---------------------------------------------------------------------------
// Launch
// ---------------------------------------------------------------------------
extern "C" void kernel_launch(void* const* d_in, const int* in_sizes, int n_in,
                              void* d_out, int out_size) {
    (void)in_sizes; (void)n_in; (void)out_size;
    const float* x      = (const float*)d_in[0];   // [8,1024,768]
    const float* w_qkv  = (const float*)d_in[1];   // [2304,768]
    const float* w_proj = (const float*)d_in[2];   // [768,768]
    const float* b_proj = (const float*)d_in[3];   // [768]

    float* out  = (float*)d_out;                       // [8,1024,768]
    float* attn = out + (long long)ROWS * EMBED;       // [8,12,1024,1024]

    float* qkv = nullptr;
    float* oh  = nullptr;
    cudaGetSymbolAddress((void**)&qkv, g_qkv);
    cudaGetSymbolAddress((void**)&oh,  g_oh);

    // 1) QKV projection: [8192,768] @ [2304,768]^T -> [8192,2304]
    gemm_nt<<<dim3(QKVCOLS / BN, ROWS / BM), 256>>>(
        x, EMBED, w_qkv, EMBED, qkv, QKVCOLS, EMBED, 1.0f, nullptr);

    // 2) Scores: per (b,h) S = scale * Q K^T -> attn (pre-softmax)
    gemm_scores<<<dim3(SEQ / BN, SEQ / BM, BATCH * HEADS), 256>>>(qkv, attn);

    // 3) Softmax rows in place
    softmax_rows<<<BATCH * HEADS * SEQ, 256>>>(attn);

    // 4) PV: O = P @ V -> g_oh
    gemm_pv<<<dim3(1, SEQ / BM, BATCH * HEADS), 256>>>(attn, qkv, oh);

    // 5) Output projection + bias: [8192,768] @ [768,768]^T + b -> out
    gemm_nt<<<dim3(EMBED / BN, ROWS / BM), 256>>>(
        oh, EMBED, w_proj, EMBED, out, EMBED, EMBED, 1.0f, b_proj);
}

// round 3
// speedup vs baseline: 3.1219x; 3.1219x over previous
#include <cuda_runtime.h>
#include <cuda_bf16.h>
#include <cstdint>

// ---------------------------------------------------------------------------
// Problem constants
// ---------------------------------------------------------------------------
#define BATCHN  8
#define SEQL    1024
#define EMB     768
#define NH      12
#define HD      64
#define ROWS    (BATCHN*SEQL)        // 8192
#define QKVC    (3*EMB)              // 2304
#define ZTOT    (BATCHN*NH)          // 96
#define AROWS   (ZTOT*SEQL)          // 98304
#define K_SCALE 0.125f
#define EXP_OFF 20.0f

// ---------------------------------------------------------------------------
// Device scratch (static globals; allocation-free)
// ---------------------------------------------------------------------------
__device__ __align__(16) __nv_bfloat16 g_x_hi  [ROWS*EMB];
__device__ __align__(16) __nv_bfloat16 g_x_lo  [ROWS*EMB];
__device__ __align__(16) __nv_bfloat16 g_wqkv_hi[QKVC*EMB];
__device__ __align__(16) __nv_bfloat16 g_wqkv_lo[QKVC*EMB];
__device__ __align__(16) __nv_bfloat16 g_wp_hi [EMB*EMB];
__device__ __align__(16) __nv_bfloat16 g_wp_lo [EMB*EMB];
__device__ __align__(16) __nv_bfloat16 g_qkv_hi[(size_t)ROWS*QKVC];
__device__ __align__(16) __nv_bfloat16 g_qkv_lo[(size_t)ROWS*QKVC];
__device__ __align__(16) __nv_bfloat16 g_p_hi  [(size_t)ZTOT*SEQL*SEQL];
__device__ __align__(16) __nv_bfloat16 g_p_lo  [(size_t)ZTOT*SEQL*SEQL];
__device__ __align__(16) __nv_bfloat16 g_oh_hi [ROWS*EMB];
__device__ __align__(16) __nv_bfloat16 g_oh_lo [ROWS*EMB];
__device__ float g_psum[(size_t)AROWS*32];
__device__ float g_inv [AROWS];

// ---------------------------------------------------------------------------
// Warp-MMA helpers (non-'a' target safe: ldmatrix + mma.sync, sm_80+)
// ---------------------------------------------------------------------------
__device__ __forceinline__ uint32_t smem_u32(const void* p) {
    uint32_t a;
    asm("{ .reg .u64 t; cvta.to.shared.u64 t, %1; cvt.u32.u64 %0, t; }"
        : "=r"(a) : "l"(p));
    return a;
}
__device__ __forceinline__ void ldsm_x4(uint32_t* r, uint32_t addr) {
    asm volatile("ldmatrix.sync.aligned.m8n8.x4.shared.b16 {%0,%1,%2,%3}, [%4];"
        : "=r"(r[0]), "=r"(r[1]), "=r"(r[2]), "=r"(r[3]) : "r"(addr));
}
__device__ __forceinline__ void ldsm_x2(uint32_t* r, uint32_t addr) {
    asm volatile("ldmatrix.sync.aligned.m8n8.x2.shared.b16 {%0,%1}, [%2];"
        : "=r"(r[0]), "=r"(r[1]) : "r"(addr));
}
__device__ __forceinline__ void ldsm_x2t(uint32_t* r, uint32_t addr) {
    asm volatile("ldmatrix.sync.aligned.m8n8.x2.trans.shared.b16 {%0,%1}, [%2];"
        : "=r"(r[0]), "=r"(r[1]) : "r"(addr));
}
__device__ __forceinline__ void mma_bf16(float* c, const uint32_t* a, const uint32_t* b) {
    asm volatile("mma.sync.aligned.m16n8k16.row.col.f32.bf16.bf16.f32 "
        "{%0,%1,%2,%3}, {%4,%5,%6,%7}, {%8,%9}, {%0,%1,%2,%3};"
        : "+f"(c[0]), "+f"(c[1]), "+f"(c[2]), "+f"(c[3])
        : "r"(a[0]), "r"(a[1]), "r"(a[2]), "r"(a[3]), "r"(b[0]), "r"(b[1]));
}

__device__ __forceinline__ uint32_t pack_hi(float a, float b) {
    return ((uint32_t)__bfloat16_as_ushort(__float2bfloat16(b)) << 16) |
            (uint32_t)__bfloat16_as_ushort(__float2bfloat16(a));
}
__device__ __forceinline__ uint32_t pack_lo(float a, float b) {
    __nv_bfloat16 ha = __float2bfloat16(a), hb = __float2bfloat16(b);
    float la = a - __bfloat162float(ha), lb = b - __bfloat162float(hb);
    return ((uint32_t)__bfloat16_as_ushort(__float2bfloat16(lb)) << 16) |
            (uint32_t)__bfloat16_as_ushort(__float2bfloat16(la));
}

// ---------------------------------------------------------------------------
// Tensor-core NT GEMM with bf16 hi/lo split (acc += Ah*Bh + Ah*Bl + Al*Bh).
// Block tile 128 x BN, K step 32, 8 warps.
// MODE 0: qkv proj  (A=x,  B=w_qkv)  -> qkv hi/lo                BN=128
// MODE 1: scores    (A=Q,  B=K)      -> p=exp(s/8-20) + psum     BN=128
// MODE 2: PV        (A=P,  B=V^T)    -> oh hi/lo + fp32 attn     BN=64
// MODE 3: out proj  (A=oh, B=w_proj) -> fp32 out + bias          BN=128
// ---------------------------------------------------------------------------
template<int MODE>
__global__ __launch_bounds__(256, 1)
void mma_gemm(const __nv_bfloat16* __restrict__ Ahi_base,
              const __nv_bfloat16* __restrict__ Alo_base,
              const __nv_bfloat16* __restrict__ Bhi_base,
              const __nv_bfloat16* __restrict__ Blo_base,
              float* __restrict__ fout,
              __nv_bfloat16* __restrict__ ohi,
              __nv_bfloat16* __restrict__ olo,
              const float* __restrict__ aux) {
    constexpr int NJ     = (MODE == 2) ? 2 : 4;       // n8-tiles per warp
    constexpr int KTOT   = (MODE == 1) ? 64 : ((MODE == 2) ? 1024 : 768);
    constexpr int NSTAGE = KTOT / 32;
    constexpr int LDS_A  = 40;                        // padded (32+8) bf16
    constexpr int LDS_B  = (MODE == 2) ? 72 : 40;     // MODE2: [k=32][n=64+8]
    constexpr int BROWS  = (MODE == 2) ? 32 : 128;

    __shared__ __align__(16) __nv_bfloat16 sAh[128 * LDS_A];
    __shared__ __align__(16) __nv_bfloat16 sAl[128 * LDS_A];
    __shared__ __align__(16) __nv_bfloat16 sBh[BROWS * LDS_B];
    __shared__ __align__(16) __nv_bfloat16 sBl[BROWS * LDS_B];

    const int tid  = threadIdx.x;
    const int lane = tid & 31;
    const int wid  = tid >> 5;
    const int wm   = wid >> 2;          // 0..1 (m64)
    const int wn   = wid & 3;           // 0..3
    const int l15  = lane & 15;
    const int bx = blockIdx.x, by = blockIdx.y, bz = blockIdx.z;
    const int bb = bz / NH, hh = bz % NH;

    // ---- gmem tile bases ----
    const __nv_bfloat16 *Ah, *Al, *Bh, *Bl;
    long long LDA = 0, LDB = 0;
    if (MODE == 0 || MODE == 3) {
        LDA = EMB; LDB = EMB;
        Ah = Ahi_base + (long long)by * 128 * EMB;
        Al = Alo_base + (long long)by * 128 * EMB;
        Bh = Bhi_base + (long long)bx * 128 * EMB;
        Bl = Blo_base + (long long)bx * 128 * EMB;
    } else if (MODE == 1) {
        LDA = QKVC; LDB = QKVC;
        long long ao = ((long long)bb * SEQL + by * 128) * QKVC + hh * HD;
        long long bo = ((long long)bb * SEQL + bx * 128) * QKVC + EMB + hh * HD;
        Ah = Ahi_base + ao; Al = Alo_base + ao;
        Bh = Bhi_base + bo; Bl = Blo_base + bo;
    } else {
        LDA = SEQL; LDB = QKVC;
        long long ao = (long long)bz * SEQL * SEQL + (long long)by * 128 * SEQL;
        Ah = Ahi_base + ao; Al = Alo_base + ao;
        Bh = Bhi_base;      Bl = Blo_base;      // V: offset computed per stage
    }
    float* attn_tile = nullptr;
    if (MODE == 2)
        attn_tile = fout + (long long)bz * SEQL * SEQL + (long long)by * 128 * SEQL;
    const long long auxbase = (MODE == 2) ? ((long long)bz * SEQL + by * 128) : 0;

    // ---- loader coordinates ----
    const int arow0 = tid >> 2;            // rows 0..63
    const int acol  = (tid & 3) * 8;       // 4 chunks of 8 per 32-col row
    const int arow1 = arow0 + 64;
    const int brow  = tid >> 3;            // MODE2: 0..31
    const int bcol  = (tid & 7) * 8;

    uint4 pAh[2], pAl[2], pBh[2], pBl[2];

    auto LOAD = [&](int s) {
        const long long k0 = (long long)s * 32;
        pAh[0] = *(const uint4*)(Ah + (long long)arow0 * LDA + k0 + acol);
        pAl[0] = *(const uint4*)(Al + (long long)arow0 * LDA + k0 + acol);
        pAh[1] = *(const uint4*)(Ah + (long long)arow1 * LDA + k0 + acol);
        pAl[1] = *(const uint4*)(Al + (long long)arow1 * LDA + k0 + acol);
        if (MODE != 2) {
            pBh[0] = *(const uint4*)(Bh + (long long)arow0 * LDB + k0 + acol);
            pBl[0] = *(const uint4*)(Bl + (long long)arow0 * LDB + k0 + acol);
            pBh[1] = *(const uint4*)(Bh + (long long)arow1 * LDB + k0 + acol);
            pBl[1] = *(const uint4*)(Bl + (long long)arow1 * LDB + k0 + acol);
        } else {
            long long vo = ((long long)bb * SEQL + s * 32 + brow) * QKVC + 2 * EMB + hh * HD + bcol;
            pBh[0] = *(const uint4*)(Bh + vo);
            pBl[0] = *(const uint4*)(Bl + vo);
        }
    };
    auto STORE = [&](int s) {
        *(uint4*)(sAh + arow0 * LDS_A + acol) = pAh[0];
        *(uint4*)(sAl + arow0 * LDS_A + acol) = pAl[0];
        *(uint4*)(sAh + arow1 * LDS_A + acol) = pAh[1];
        *(uint4*)(sAl + arow1 * LDS_A + acol) = pAl[1];
        if (MODE != 2) {
            *(uint4*)(sBh + arow0 * LDS_B + acol) = pBh[0];
            *(uint4*)(sBl + arow0 * LDS_B + acol) = pBl[0];
            *(uint4*)(sBh + arow1 * LDS_B + acol) = pBh[1];
            *(uint4*)(sBl + arow1 * LDS_B + acol) = pBl[1];
        } else {
            *(uint4*)(sBh + brow * LDS_B + bcol) = pBh[0];
            *(uint4*)(sBl + brow * LDS_B + bcol) = pBl[0];
            // normalized fp32 attn output, streamed while P passes through
            #pragma unroll
            for (int cch = 0; cch < 2; cch++) {
                int r = (cch == 0) ? arow0 : arow1;
                float iv = aux[auxbase + r];
                const __nv_bfloat16* eh = (const __nv_bfloat16*)&pAh[cch];
                const __nv_bfloat16* el = (const __nv_bfloat16*)&pAl[cch];
                long long ab = (long long)r * SEQL + s * 32 + acol;
                float4 o0, o1;
                o0.x = (__bfloat162float(eh[0]) + __bfloat162float(el[0])) * iv;
                o0.y = (__bfloat162float(eh[1]) + __bfloat162float(el[1])) * iv;
                o0.z = (__bfloat162float(eh[2]) + __bfloat162float(el[2])) * iv;
                o0.w = (__bfloat162float(eh[3]) + __bfloat162float(el[3])) * iv;
                o1.x = (__bfloat162float(eh[4]) + __bfloat162float(el[4])) * iv;
                o1.y = (__bfloat162float(eh[5]) + __bfloat162float(el[5])) * iv;
                o1.z = (__bfloat162float(eh[6]) + __bfloat162float(el[6])) * iv;
                o1.w = (__bfloat162float(eh[7]) + __bfloat162float(el[7])) * iv;
                *(float4*)(attn_tile + ab)     = o0;
                *(float4*)(attn_tile + ab + 4) = o1;
            }
        }
    };

    float acc[4][NJ][4];
    #pragma unroll
    for (int i = 0; i < 4; i++)
        #pragma unroll
        for (int j = 0; j < NJ; j++)
            #pragma unroll
            for (int e = 0; e < 4; e++) acc[i][j][e] = 0.f;

    const uint32_t uAh = smem_u32(sAh), uAl = smem_u32(sAl);
    const uint32_t uBh = smem_u32(sBh), uBl = smem_u32(sBl);

    LOAD(0);
    for (int s = 0; s < NSTAGE; s++) {
        STORE(s);
        __syncthreads();
        if (s + 1 < NSTAGE) LOAD(s + 1);

        #pragma unroll
        for (int ks = 0; ks < 2; ks++) {
            uint32_t bh[NJ][2], bl[NJ][2];
            #pragma unroll
            for (int j = 0; j < NJ; j++) {
                uint32_t off;
                if (MODE == 2) {
                    int kr = ks * 16 + l15;
                    int nc = wn * 16 + j * 8;
                    off = (uint32_t)(kr * LDS_B + nc) * 2;
                    ldsm_x2t(bh[j], uBh + off);
                    ldsm_x2t(bl[j], uBl + off);
                } else {
                    int nr = wn * 32 + j * 8 + (l15 & 7);
                    int kc = ks * 16 + (l15 >> 3) * 8;
                    off = (uint32_t)(nr * LDS_B + kc) * 2;
                    ldsm_x2(bh[j], uBh + off);
                    ldsm_x2(bl[j], uBl + off);
                }
            }
            #pragma unroll
            for (int i = 0; i < 4; i++) {
                int ar = wm * 64 + i * 16 + l15;
                int ac = ks * 16 + (lane >> 4) * 8;
                uint32_t aoff = (uint32_t)(ar * LDS_A + ac) * 2;
                uint32_t ah[4], al[4];
                ldsm_x4(ah, uAh + aoff);
                #pragma unroll
                for (int j = 0; j < NJ; j++) mma_bf16(acc[i][j], ah, bh[j]);
                ldsm_x4(al, uAl + aoff);
                #pragma unroll
                for (int j = 0; j < NJ; j++) mma_bf16(acc[i][j], ah, bl[j]);
                #pragma unroll
                for (int j = 0; j < NJ; j++) mma_bf16(acc[i][j], al, bh[j]);
            }
        }
        __syncthreads();
    }

    // ---- epilogue ----
    const int g = lane >> 2, t = lane & 3;
    #pragma unroll
    for (int i = 0; i < 4; i++) {
        const int r0 = wm * 64 + i * 16 + g;
        const int r1 = r0 + 8;
        const int m0 = by * 128 + r0;
        const int m1 = by * 128 + r1;
        float s0 = 0.f, s1 = 0.f;
        float inv0 = 0.f, inv1 = 0.f;
        if (MODE == 2) { inv0 = aux[auxbase + r0]; inv1 = aux[auxbase + r1]; }

        #pragma unroll
        for (int j = 0; j < NJ; j++) {
            float c0 = acc[i][j][0], c1 = acc[i][j][1];
            float c2 = acc[i][j][2], c3 = acc[i][j][3];
            if (MODE == 0) {
                int n = bx * 128 + wn * 32 + j * 8 + 2 * t;
                long long o0 = (long long)m0 * QKVC + n;
                long long o1 = (long long)m1 * QKVC + n;
                *(uint32_t*)(ohi + o0) = pack_hi(c0, c1);
                *(uint32_t*)(olo + o0) = pack_lo(c0, c1);
                *(uint32_t*)(ohi + o1) = pack_hi(c2, c3);
                *(uint32_t*)(olo + o1) = pack_lo(c2, c3);
            } else if (MODE == 1) {
                float v0 = __expf(fmaf(c0, K_SCALE, -EXP_OFF));
                float v1 = __expf(fmaf(c1, K_SCALE, -EXP_OFF));
                float v2 = __expf(fmaf(c2, K_SCALE, -EXP_OFF));
                float v3 = __expf(fmaf(c3, K_SCALE, -EXP_OFF));
                s0 += v0 + v1; s1 += v2 + v3;
                int n = bx * 128 + wn * 32 + j * 8 + 2 * t;
                long long o0 = ((long long)bz * SEQL + m0) * SEQL + n;
                long long o1 = ((long long)bz * SEQL + m1) * SEQL + n;
                *(uint32_t*)(ohi + o0) = pack_hi(v0, v1);
                *(uint32_t*)(olo + o0) = pack_lo(v0, v1);
                *(uint32_t*)(ohi + o1) = pack_hi(v2, v3);
                *(uint32_t*)(olo + o1) = pack_lo(v2, v3);
            } else if (MODE == 2) {
                float v0 = c0 * inv0, v1 = c1 * inv0;
                float v2 = c2 * inv1, v3 = c3 * inv1;
                int n = hh * HD + wn * 16 + j * 8 + 2 * t;
                long long o0 = ((long long)bb * SEQL + m0) * EMB + n;
                long long o1 = ((long long)bb * SEQL + m1) * EMB + n;
                *(uint32_t*)(ohi + o0) = pack_hi(v0, v1);
                *(uint32_t*)(olo + o0) = pack_lo(v0, v1);
                *(uint32_t*)(ohi + o1) = pack_hi(v2, v3);
                *(uint32_t*)(olo + o1) = pack_lo(v2, v3);
            } else {
                int n = bx * 128 + wn * 32 + j * 8 + 2 * t;
                float2 w0 = { c0 + aux[n], c1 + aux[n + 1] };
                float2 w1 = { c2 + aux[n], c3 + aux[n + 1] };
                *(float2*)(fout + (long long)m0 * EMB + n) = w0;
                *(float2*)(fout + (long long)m1 * EMB + n) = w1;
            }
        }
        if (MODE == 1) {
            s0 += __shfl_xor_sync(0xffffffffu, s0, 1);
            s0 += __shfl_xor_sync(0xffffffffu, s0, 2);
            s1 += __shfl_xor_sync(0xffffffffu, s1, 1);
            s1 += __shfl_xor_sync(0xffffffffu, s1, 2);
            if (t == 0) {
                fout[((long long)bz * SEQL + m0) * 32 + bx * 4 + wn] = s0;
                fout[((long long)bz * SEQL + m1) * 32 + bx * 4 + wn] = s1;
            }
        }
    }
}

// ---------------------------------------------------------------------------
// fp32 -> bf16 hi/lo split
// ---------------------------------------------------------------------------
__global__ void split_hilo(const float* __restrict__ src,
                           __nv_bfloat16* __restrict__ hi,
                           __nv_bfloat16* __restrict__ lo, int n) {
    int i = blockIdx.x * 256 + threadIdx.x;
    if (i < n) {
        float v = src[i];
        __nv_bfloat16 h = __float2bfloat16(v);
        hi[i] = h;
        lo[i] = __float2bfloat16(v - __bfloat162float(h));
    }
}

// 32 partials per row -> 1/sum
__global__ void inv_rows(const float* __restrict__ psum, float* __restrict__ inv) {
    int r = blockIdx.x * 256 + threadIdx.x;
    if (r < AROWS) {
        float s = 0.f;
        #pragma unroll
        for (int j = 0; j < 32; j++) s += psum[(long long)r * 32 + j];
        inv[r] = 1.0f / s;
    }
}

// ---------------------------------------------------------------------------
// Launch
// ---------------------------------------------------------------------------
extern "C" void kernel_launch(void* const* d_in, const int* in_sizes, int n_in,
                              void* d_out, int out_size) {
    (void)in_sizes; (void)n_in; (void)out_size;
    const float* x      = (const float*)d_in[0];
    const float* w_qkv  = (const float*)d_in[1];
    const float* w_proj = (const float*)d_in[2];
    const float* b_proj = (const float*)d_in[3];

    float* out  = (float*)d_out;
    float* attn = out + (long long)ROWS * EMB;

    __nv_bfloat16 *xh, *xl, *wqh, *wql, *wph, *wpl, *qh, *ql, *ph, *pl, *ohh, *ohl;
    float *psum, *inv;
    cudaGetSymbolAddress((void**)&xh,  g_x_hi);    cudaGetSymbolAddress((void**)&xl,  g_x_lo);
    cudaGetSymbolAddress((void**)&wqh, g_wqkv_hi); cudaGetSymbolAddress((void**)&wql, g_wqkv_lo);
    cudaGetSymbolAddress((void**)&wph, g_wp_hi);   cudaGetSymbolAddress((void**)&wpl, g_wp_lo);
    cudaGetSymbolAddress((void**)&qh,  g_qkv_hi);  cudaGetSymbolAddress((void**)&ql,  g_qkv_lo);
    cudaGetSymbolAddress((void**)&ph,  g_p_hi);    cudaGetSymbolAddress((void**)&pl,  g_p_lo);
    cudaGetSymbolAddress((void**)&ohh, g_oh_hi);   cudaGetSymbolAddress((void**)&ohl, g_oh_lo);
    cudaGetSymbolAddress((void**)&psum, g_psum);   cudaGetSymbolAddress((void**)&inv,  g_inv);

    // 0) hi/lo splits of fp32 inputs
    split_hilo<<<(ROWS*EMB + 255)/256, 256>>>(x, xh, xl, ROWS*EMB);
    split_hilo<<<(QKVC*EMB + 255)/256, 256>>>(w_qkv, wqh, wql, QKVC*EMB);
    split_hilo<<<(EMB*EMB + 255)/256, 256>>>(w_proj, wph, wpl, EMB*EMB);

    // 1) QKV projection -> qkv hi/lo
    mma_gemm<0><<<dim3(QKVC/128, ROWS/128), 256>>>(
        xh, xl, wqh, wql, nullptr, qh, ql, nullptr);

    // 2) Scores + exp -> p hi/lo + row partial sums (32 per row)
    mma_gemm<1><<<dim3(8, 8, ZTOT), 256>>>(
        qh, ql, qh, ql, psum, ph, pl, nullptr);

    // 3) 1/rowsum
    inv_rows<<<(AROWS + 255)/256, 256>>>(psum, inv);

    // 4) PV -> oh hi/lo; streams out normalized fp32 attn
    mma_gemm<2><<<dim3(1, 8, ZTOT), 256>>>(
        ph, pl, qh, ql, attn, ohh, ohl, inv);

    // 5) Output projection + bias -> fp32 out
    mma_gemm<3><<<dim3(EMB/128, ROWS/128), 256>>>(
        ohh, ohl, wph, wpl, out, nullptr, nullptr, b_proj);
}